// round 1
// baseline (speedup 1.0000x reference)
#include <cuda_runtime.h>
#include <cstdint>

// Problem constants
#define T_TOK  8192          // B*S tokens
#define DDIM   1024
#define HDIM   2048
#define NEXP   8
#define TOPK   2
#define ROWS_TOT 24576       // T*K routed rows + T shared rows
#define MAXTILES 200         // sum ceil(c_e/128) <= 136, + 64 shared tiles

// ---------------- scratch (__device__ globals; no allocation allowed) -------
__device__ float g_H1[(size_t)ROWS_TOT * HDIM];   // GEMM1(W1) out, then U=silu(H1)*H3 in place
__device__ float g_H3[(size_t)ROWS_TOT * HDIM];   // GEMM1(W3) out
__device__ float g_Y [(size_t)ROWS_TOT * DDIM];   // per-slot routed/shared outputs (scaled)
__device__ int   g_rows [ROWS_TOT];               // grouped row -> token*4 + k   (k=0,1 routed, 2 shared)
__device__ float g_wslot[ROWS_TOT];               // slot (t*3+k) -> combine weight
__device__ int   g_tok_e[T_TOK * TOPK];           // (t,k) -> expert id
__device__ int   g_cnt [16];
__device__ int   g_fill[16];
__device__ int   g_off [16];                      // exclusive offsets, off[9] = ROWS_TOT
__device__ int   g_tile_e[MAXTILES + 8];
__device__ int   g_tile_m[MAXTILES + 8];
__device__ int   g_ntiles;

// ---------------- small kernels --------------------------------------------
__global__ void zero_kernel() {
    if (threadIdx.x < 16) { g_cnt[threadIdx.x] = 0; g_fill[threadIdx.x] = 0; }
}

// one warp per token: scores = hf @ Wg^T, softmax, top-2, renormalize
__global__ void gate_kernel(const float* __restrict__ hf, const float* __restrict__ Wg) {
    int wid  = (blockIdx.x * blockDim.x + threadIdx.x) >> 5;
    int lane = threadIdx.x & 31;
    if (wid >= T_TOK) return;
    int t = wid;

    float s[NEXP];
#pragma unroll
    for (int e = 0; e < NEXP; e++) s[e] = 0.f;
    const float* x = hf + (size_t)t * DDIM;
    for (int d = lane; d < DDIM; d += 32) {
        float xv = x[d];
#pragma unroll
        for (int e = 0; e < NEXP; e++) s[e] += xv * Wg[e * DDIM + d];
    }
#pragma unroll
    for (int e = 0; e < NEXP; e++) {
#pragma unroll
        for (int o = 16; o; o >>= 1) s[e] += __shfl_xor_sync(0xffffffffu, s[e], o);
    }
    if (lane == 0) {
        float m = s[0];
#pragma unroll
        for (int e = 1; e < NEXP; e++) m = fmaxf(m, s[e]);
        float p[NEXP];
#pragma unroll
        for (int e = 0; e < NEXP; e++) p[e] = __expf(s[e] - m);
        // top-2, first index wins on ties (matches jax top_k)
        float v0 = -1.f, v1 = -1.f; int i0 = 0, i1 = 0;
#pragma unroll
        for (int e = 0; e < NEXP; e++) {
            if (p[e] > v0)      { v1 = v0; i1 = i0; v0 = p[e]; i0 = e; }
            else if (p[e] > v1) { v1 = p[e]; i1 = e; }
        }
        float inv = 1.f / (v0 + v1);
        g_tok_e[t * 2 + 0] = i0;
        g_tok_e[t * 2 + 1] = i1;
        g_wslot[t * 3 + 0] = v0 * inv;
        g_wslot[t * 3 + 1] = v1 * inv;
        g_wslot[t * 3 + 2] = 1.f;
        atomicAdd(&g_cnt[i0], 1);
        atomicAdd(&g_cnt[i1], 1);
        // shared-expert group (group 8) rows are identity-ordered
        g_rows[T_TOK * TOPK + t] = t * 4 + 2;
    }
}

__global__ void setup_kernel() {
    g_off[0] = 0;
    for (int e = 0; e < NEXP; e++) g_off[e + 1] = g_off[e] + g_cnt[e];
    g_off[NEXP + 1] = g_off[NEXP] + T_TOK;   // == ROWS_TOT
    int nt = 0;
    for (int e = 0; e <= NEXP; e++) {
        int Me = g_off[e + 1] - g_off[e];
        for (int j = 0; j < Me; j += 128) { g_tile_e[nt] = e; g_tile_m[nt] = j; nt++; }
    }
    g_ntiles = nt;
}

__global__ void scatter_kernel() {
    int i = blockIdx.x * blockDim.x + threadIdx.x;
    if (i >= T_TOK * TOPK) return;
    int e = g_tok_e[i];
    int pos = atomicAdd(&g_fill[e], 1);
    g_rows[g_off[e] + pos] = (i >> 1) * 4 + (i & 1);
}

__global__ void silu_mul_kernel() {
    size_t i = (size_t)blockIdx.x * blockDim.x + threadIdx.x;
    const size_t n4 = (size_t)ROWS_TOT * HDIM / 4;
    if (i >= n4) return;
    float4 a = ((const float4*)g_H1)[i];
    float4 b = ((const float4*)g_H3)[i];
    float4 r;
    r.x = (a.x / (1.f + __expf(-a.x))) * b.x;
    r.y = (a.y / (1.f + __expf(-a.y))) * b.y;
    r.z = (a.z / (1.f + __expf(-a.z))) * b.z;
    r.w = (a.w / (1.f + __expf(-a.w))) * b.w;
    ((float4*)g_H1)[i] = r;
}

__global__ void combine_kernel(float* __restrict__ out) {
    int i = blockIdx.x * blockDim.x + threadIdx.x;   // over float4s of output
    if (i >= T_TOK * DDIM / 4) return;
    int t  = i / (DDIM / 4);
    int d4 = i % (DDIM / 4);
    const float4* Y = (const float4*)g_Y;
    float4 a = Y[(size_t)(t * 3 + 0) * (DDIM / 4) + d4];
    float4 b = Y[(size_t)(t * 3 + 1) * (DDIM / 4) + d4];
    float4 c = Y[(size_t)(t * 3 + 2) * (DDIM / 4) + d4];
    ((float4*)out)[i] = make_float4(a.x + b.x + c.x, a.y + b.y + c.y,
                                    a.z + b.z + c.z, a.w + b.w + c.w);
}

// ---------------- tf32 grouped GEMM -----------------------------------------
__device__ __forceinline__ unsigned f2tf(float x) {
    unsigned u; asm("cvt.rna.tf32.f32 %0, %1;" : "=r"(u) : "f"(x)); return u;
}

// C[m,n] = sum_k A[m,k] * B[n,k]   (B row-major [N,K] = torch Linear weight)
// 128x128 block tile, BK=16, 8 warps of 64x32, m16n8k8 tf32 MMA.
template<int KDIM, int NDIM, bool GATHER, bool SCATTER>
__global__ __launch_bounds__(256, 1) void gemm_tf32(
    const float* __restrict__ Abase,
    const float* __restrict__ Wexp,   // [NEXP, NDIM*KDIM]
    const float* __restrict__ Wsh,    // [NDIM*KDIM]
    float* __restrict__ Cout)
{
    int tileIdx = blockIdx.y;
    if (tileIdx >= g_ntiles) return;
    const int e   = g_tile_e[tileIdx];
    const int m0  = g_tile_m[tileIdx];
    const int off = g_off[e];
    const int Me  = g_off[e + 1] - off;
    const float* B = (e < NEXP) ? (Wexp + (size_t)e * NDIM * KDIM) : Wsh;
    const int n0 = blockIdx.x * 128;

    __shared__ unsigned As[2][128][20];   // pad 20: conflict-free fragment loads
    __shared__ unsigned Bs[2][128][20];

    const int tid = threadIdx.x;
    const int lr = tid >> 2;              // loader row 0..63 (and +64)
    const int lc = (tid & 3) << 2;        // k offset 0/4/8/12

    const float* aptr0; const float* aptr1;
    {
        int ml0 = m0 + lr, ml1 = m0 + lr + 64;
        int gi0 = off + (ml0 < Me ? ml0 : 0);
        int gi1 = off + (ml1 < Me ? ml1 : 0);
        int r0  = GATHER ? (g_rows[gi0] >> 2) : gi0;
        int r1  = GATHER ? (g_rows[gi1] >> 2) : gi1;
        aptr0 = Abase + (size_t)r0 * KDIM + lc;
        aptr1 = Abase + (size_t)r1 * KDIM + lc;
    }
    const float* bptr0 = B + (size_t)(n0 + lr)      * KDIM + lc;
    const float* bptr1 = B + (size_t)(n0 + lr + 64) * KDIM + lc;

    const int wid = tid >> 5, lane = tid & 31;
    const int wm = wid & 1, wn = wid >> 1;
    const int gid = lane >> 2, tig = lane & 3;
    const int mb = wm * 64, nb = wn * 32;

    float acc[4][4][4];
#pragma unroll
    for (int i = 0; i < 4; i++)
#pragma unroll
        for (int j = 0; j < 4; j++)
#pragma unroll
            for (int q = 0; q < 4; q++) acc[i][j][q] = 0.f;

    float4 sa0, sa1, sb0, sb1;

#define STAGE_STORE(buf)                                                                 \
    do {                                                                                 \
        unsigned* p;                                                                     \
        p = &As[buf][lr][lc];      p[0]=f2tf(sa0.x); p[1]=f2tf(sa0.y); p[2]=f2tf(sa0.z); p[3]=f2tf(sa0.w); \
        p = &As[buf][lr + 64][lc]; p[0]=f2tf(sa1.x); p[1]=f2tf(sa1.y); p[2]=f2tf(sa1.z); p[3]=f2tf(sa1.w); \
        p = &Bs[buf][lr][lc];      p[0]=f2tf(sb0.x); p[1]=f2tf(sb0.y); p[2]=f2tf(sb0.z); p[3]=f2tf(sb0.w); \
        p = &Bs[buf][lr + 64][lc]; p[0]=f2tf(sb1.x); p[1]=f2tf(sb1.y); p[2]=f2tf(sb1.z); p[3]=f2tf(sb1.w); \
    } while (0)

    // prologue: stage k-tile 0
    sa0 = *(const float4*)(aptr0);
    sa1 = *(const float4*)(aptr1);
    sb0 = *(const float4*)(bptr0);
    sb1 = *(const float4*)(bptr1);
    STAGE_STORE(0);
    __syncthreads();

    const int KT = KDIM / 16;
    int cur = 0;
    for (int kt = 0; kt < KT; kt++) {
        if (kt + 1 < KT) {
            int k0 = (kt + 1) * 16;
            sa0 = *(const float4*)(aptr0 + k0);
            sa1 = *(const float4*)(aptr1 + k0);
            sb0 = *(const float4*)(bptr0 + k0);
            sb1 = *(const float4*)(bptr1 + k0);
        }
#pragma unroll
        for (int kk = 0; kk < 16; kk += 8) {
            unsigned af[4][4], bf[4][2];
#pragma unroll
            for (int mi = 0; mi < 4; mi++) {
                int r = mb + mi * 16 + gid;
                af[mi][0] = As[cur][r    ][kk + tig];
                af[mi][1] = As[cur][r + 8][kk + tig];
                af[mi][2] = As[cur][r    ][kk + tig + 4];
                af[mi][3] = As[cur][r + 8][kk + tig + 4];
            }
#pragma unroll
            for (int ni = 0; ni < 4; ni++) {
                int r = nb + ni * 8 + gid;
                bf[ni][0] = Bs[cur][r][kk + tig];
                bf[ni][1] = Bs[cur][r][kk + tig + 4];
            }
#pragma unroll
            for (int mi = 0; mi < 4; mi++)
#pragma unroll
                for (int ni = 0; ni < 4; ni++) {
                    asm volatile(
                        "mma.sync.aligned.m16n8k8.row.col.f32.tf32.tf32.f32 "
                        "{%0,%1,%2,%3}, {%4,%5,%6,%7}, {%8,%9}, {%0,%1,%2,%3};\n"
                        : "+f"(acc[mi][ni][0]), "+f"(acc[mi][ni][1]),
                          "+f"(acc[mi][ni][2]), "+f"(acc[mi][ni][3])
                        : "r"(af[mi][0]), "r"(af[mi][1]), "r"(af[mi][2]), "r"(af[mi][3]),
                          "r"(bf[ni][0]), "r"(bf[ni][1]));
                }
        }
        if (kt + 1 < KT) {
            int nx = cur ^ 1;
            STAGE_STORE(nx);
        }
        __syncthreads();
        cur ^= 1;
    }
#undef STAGE_STORE

    // epilogue
#pragma unroll
    for (int mi = 0; mi < 4; mi++) {
#pragma unroll
        for (int half = 0; half < 2; half++) {
            int ml = m0 + mb + mi * 16 + gid + half * 8;
            if (ml < Me) {
                int gi = off + ml;
                size_t rowbase;
                float w = 1.f;
                if (SCATTER) {
                    int info = g_rows[gi];
                    int slot = (info >> 2) * 3 + (info & 3);
                    w = g_wslot[slot];
                    rowbase = (size_t)slot * NDIM;
                } else {
                    rowbase = (size_t)gi * NDIM;
                }
#pragma unroll
                for (int ni = 0; ni < 4; ni++) {
                    int n = n0 + nb + ni * 8 + tig * 2;
                    float2 v;
                    v.x = acc[mi][ni][half * 2 + 0] * w;
                    v.y = acc[mi][ni][half * 2 + 1] * w;
                    *(float2*)(Cout + rowbase + n) = v;
                }
            }
        }
    }
}

// ---------------- launch -----------------------------------------------------
extern "C" void kernel_launch(void* const* d_in, const int* in_sizes, int n_in,
                              void* d_out, int out_size)
{
    const float* h   = (const float*)d_in[0];
    const float* sw1 = (const float*)d_in[1];
    const float* sw2 = (const float*)d_in[2];
    const float* sw3 = (const float*)d_in[3];
    const float* W1  = (const float*)d_in[4];
    const float* W2  = (const float*)d_in[5];
    const float* W3  = (const float*)d_in[6];
    const float* Wg  = (const float*)d_in[7];
    float* out = (float*)d_out;

    void *pH1, *pH3, *pY;
    cudaGetSymbolAddress(&pH1, g_H1);
    cudaGetSymbolAddress(&pH3, g_H3);
    cudaGetSymbolAddress(&pY,  g_Y);

    zero_kernel<<<1, 32>>>();
    gate_kernel<<<T_TOK / 8, 256>>>(h, Wg);
    setup_kernel<<<1, 1>>>();
    scatter_kernel<<<(T_TOK * TOPK + 255) / 256, 256>>>();

    dim3 grid1(HDIM / 128, MAXTILES);   // N = 2048
    dim3 grid2(DDIM / 128, MAXTILES);   // N = 1024

    gemm_tf32<DDIM, HDIM, true,  false><<<grid1, 256>>>(h, W1, sw1, (float*)pH1);
    gemm_tf32<DDIM, HDIM, true,  false><<<grid1, 256>>>(h, W3, sw3, (float*)pH3);

    silu_mul_kernel<<<(int)(((size_t)ROWS_TOT * HDIM / 4 + 255) / 256), 256>>>();

    gemm_tf32<HDIM, DDIM, false, true><<<grid2, 256>>>((const float*)pH1, W2, sw2, (float*)pY);

    combine_kernel<<<(T_TOK * DDIM / 4 + 255) / 256, 256>>>(out);
}

// round 2
// speedup vs baseline: 1.5618x; 1.5618x over previous
#include <cuda_runtime.h>
#include <cstdint>

// Problem constants
#define T_TOK  8192
#define DDIM   1024
#define HDIM   2048
#define NEXP   8
#define TOPK   2
#define ROWS_TOT 24576       // T*K routed rows + T shared rows
#define MAXTILES 200
#define LDSS   36            // smem row stride (floats), conflict-free

// ---------------- scratch ----------------------------------------------------
__device__ float g_U[(size_t)ROWS_TOT * HDIM];    // fused GEMM1 output: silu(h1)*h3
__device__ float g_Y[(size_t)ROWS_TOT * DDIM];    // per-slot outputs (scaled)
__device__ int   g_rows [ROWS_TOT];               // grouped row -> token*4 + k
__device__ float g_wslot[T_TOK * 3];
__device__ int   g_tok_e[T_TOK * TOPK];
__device__ int   g_cnt [16];
__device__ int   g_fill[16];
__device__ int   g_off [16];
__device__ int   g_tile_e[MAXTILES + 8];
__device__ int   g_tile_m[MAXTILES + 8];
__device__ int   g_ntiles;

// ---------------- small kernels ----------------------------------------------
__global__ void zero_kernel() {
    if (threadIdx.x < 16) { g_cnt[threadIdx.x] = 0; g_fill[threadIdx.x] = 0; }
}

__global__ void gate_kernel(const float* __restrict__ hf, const float* __restrict__ Wg) {
    int wid  = (blockIdx.x * blockDim.x + threadIdx.x) >> 5;
    int lane = threadIdx.x & 31;
    if (wid >= T_TOK) return;
    int t = wid;

    float s[NEXP];
#pragma unroll
    for (int e = 0; e < NEXP; e++) s[e] = 0.f;
    const float* x = hf + (size_t)t * DDIM;
    for (int d = lane; d < DDIM; d += 32) {
        float xv = x[d];
#pragma unroll
        for (int e = 0; e < NEXP; e++) s[e] += xv * Wg[e * DDIM + d];
    }
#pragma unroll
    for (int e = 0; e < NEXP; e++) {
#pragma unroll
        for (int o = 16; o; o >>= 1) s[e] += __shfl_xor_sync(0xffffffffu, s[e], o);
    }
    if (lane == 0) {
        float m = s[0];
#pragma unroll
        for (int e = 1; e < NEXP; e++) m = fmaxf(m, s[e]);
        float p[NEXP];
#pragma unroll
        for (int e = 0; e < NEXP; e++) p[e] = __expf(s[e] - m);
        float v0 = -1.f, v1 = -1.f; int i0 = 0, i1 = 0;
#pragma unroll
        for (int e = 0; e < NEXP; e++) {
            if (p[e] > v0)      { v1 = v0; i1 = i0; v0 = p[e]; i0 = e; }
            else if (p[e] > v1) { v1 = p[e]; i1 = e; }
        }
        float inv = 1.f / (v0 + v1);
        g_tok_e[t * 2 + 0] = i0;
        g_tok_e[t * 2 + 1] = i1;
        g_wslot[t * 3 + 0] = v0 * inv;
        g_wslot[t * 3 + 1] = v1 * inv;
        g_wslot[t * 3 + 2] = 1.f;
        atomicAdd(&g_cnt[i0], 1);
        atomicAdd(&g_cnt[i1], 1);
        g_rows[T_TOK * TOPK + t] = t * 4 + 2;   // shared-expert group rows
    }
}

__global__ void setup_kernel() {
    g_off[0] = 0;
    for (int e = 0; e < NEXP; e++) g_off[e + 1] = g_off[e] + g_cnt[e];
    g_off[NEXP + 1] = g_off[NEXP] + T_TOK;
    int nt = 0;
    for (int e = 0; e <= NEXP; e++) {
        int Me = g_off[e + 1] - g_off[e];
        for (int j = 0; j < Me; j += 128) { g_tile_e[nt] = e; g_tile_m[nt] = j; nt++; }
    }
    g_ntiles = nt;
}

__global__ void scatter_kernel() {
    int i = blockIdx.x * blockDim.x + threadIdx.x;
    if (i >= T_TOK * TOPK) return;
    int e = g_tok_e[i];
    int pos = atomicAdd(&g_fill[e], 1);
    g_rows[g_off[e] + pos] = (i >> 1) * 4 + (i & 1);
}

__global__ void combine_kernel(float* __restrict__ out) {
    int i = blockIdx.x * blockDim.x + threadIdx.x;
    if (i >= T_TOK * DDIM / 4) return;
    int t  = i / (DDIM / 4);
    int d4 = i % (DDIM / 4);
    const float4* Y = (const float4*)g_Y;
    float4 a = Y[(size_t)(t * 3 + 0) * (DDIM / 4) + d4];
    float4 b = Y[(size_t)(t * 3 + 1) * (DDIM / 4) + d4];
    float4 c = Y[(size_t)(t * 3 + 2) * (DDIM / 4) + d4];
    ((float4*)out)[i] = make_float4(a.x + b.x + c.x, a.y + b.y + c.y,
                                    a.z + b.z + c.z, a.w + b.w + c.w);
}

// ---------------- tf32 helpers ----------------------------------------------
__device__ __forceinline__ unsigned f2tf(float x) {
    unsigned u; asm("cvt.rna.tf32.f32 %0, %1;" : "=r"(u) : "f"(x)); return u;
}
__device__ __forceinline__ void mma_tf32(float* c, const unsigned* a, const unsigned* b) {
    asm volatile(
        "mma.sync.aligned.m16n8k8.row.col.f32.tf32.tf32.f32 "
        "{%0,%1,%2,%3}, {%4,%5,%6,%7}, {%8,%9}, {%0,%1,%2,%3};\n"
        : "+f"(c[0]), "+f"(c[1]), "+f"(c[2]), "+f"(c[3])
        : "r"(a[0]), "r"(a[1]), "r"(a[2]), "r"(a[3]), "r"(b[0]), "r"(b[1]));
}
__device__ __forceinline__ float silu(float x) { return x / (1.f + __expf(-x)); }

// ---------------- fused GEMM1: U = silu(A@W1^T) * (A@W3^T), grouped ----------
// block tile 128m x 128h, BK=32, 512 threads (16 warps, warp = 32m x 32h x 2 weights)
#define SMEM1_BYTES ((2 * 128 * LDSS + 2 * 256 * LDSS) * 4)
__global__ __launch_bounds__(512, 1) void gemm1_fused(
    const float* __restrict__ A,
    const float* __restrict__ W1, const float* __restrict__ sw1,
    const float* __restrict__ W3, const float* __restrict__ sw3,
    float* __restrict__ U)
{
    int tileIdx = blockIdx.y;
    if (tileIdx >= g_ntiles) return;
    const int e   = g_tile_e[tileIdx];
    const int m0  = g_tile_m[tileIdx];
    const int off = g_off[e];
    const int Me  = g_off[e + 1] - off;
    const float* B1 = (e < NEXP) ? (W1 + (size_t)e * HDIM * DDIM) : sw1;
    const float* B3 = (e < NEXP) ? (W3 + (size_t)e * HDIM * DDIM) : sw3;
    const int n0 = blockIdx.x * 128;

    extern __shared__ unsigned sm1[];
    unsigned* As = sm1;                       // [2][128*LDSS]
    unsigned* Bs = sm1 + 2 * 128 * LDSS;      // [2][256*LDSS]

    const int tid = threadIdx.x;

    // ---- loader setup: A = 2 x float4 / thread, B = 4 x float4 / thread ----
    const float* aptr[2];
#pragma unroll
    for (int j = 0; j < 2; j++) {
        int idx = tid + j * 512;
        int row = idx >> 3, kc = (idx & 7) * 4;
        int ml = m0 + row;
        int gi = off + (ml < Me ? ml : 0);
        int tok = g_rows[gi] >> 2;
        aptr[j] = A + (size_t)tok * DDIM + kc;
    }
    const float* bptr[4];
#pragma unroll
    for (int j = 0; j < 4; j++) {
        int idx = tid + j * 512;
        int row = idx >> 3, kc = (idx & 7) * 4;
        const float* Bsrc = (row < 128) ? (B1 + (size_t)(n0 + row) * DDIM)
                                        : (B3 + (size_t)(n0 + row - 128) * DDIM);
        bptr[j] = Bsrc + kc;
    }

    const int wid = tid >> 5, lane = tid & 31;
    const int mb = (wid & 3) * 32, nb = (wid >> 2) * 32;
    const int gid = lane >> 2, tig = lane & 3;

    float acc1[2][4][4], acc3[2][4][4];
#pragma unroll
    for (int mi = 0; mi < 2; mi++)
#pragma unroll
        for (int ni = 0; ni < 4; ni++)
#pragma unroll
            for (int q = 0; q < 4; q++) { acc1[mi][ni][q] = 0.f; acc3[mi][ni][q] = 0.f; }

    float4 ra[2], rb[4];

#define F1_STORE(buf)                                                                     \
    do {                                                                                  \
        unsigned* ab = As + (buf) * 128 * LDSS;                                           \
        unsigned* bb = Bs + (buf) * 256 * LDSS;                                           \
        _Pragma("unroll")                                                                 \
        for (int j = 0; j < 2; j++) {                                                     \
            int idx = tid + j * 512;                                                      \
            int st = (idx >> 3) * LDSS + (idx & 7) * 4;                                   \
            *(uint4*)(ab + st) = make_uint4(f2tf(ra[j].x), f2tf(ra[j].y),                 \
                                            f2tf(ra[j].z), f2tf(ra[j].w));                \
        }                                                                                 \
        _Pragma("unroll")                                                                 \
        for (int j = 0; j < 4; j++) {                                                     \
            int idx = tid + j * 512;                                                      \
            int st = (idx >> 3) * LDSS + (idx & 7) * 4;                                   \
            *(uint4*)(bb + st) = make_uint4(f2tf(rb[j].x), f2tf(rb[j].y),                 \
                                            f2tf(rb[j].z), f2tf(rb[j].w));                \
        }                                                                                 \
    } while (0)

    // prologue
#pragma unroll
    for (int j = 0; j < 2; j++) ra[j] = *(const float4*)(aptr[j]);
#pragma unroll
    for (int j = 0; j < 4; j++) rb[j] = *(const float4*)(bptr[j]);
    F1_STORE(0);
    __syncthreads();

    const int KT = DDIM / 32;   // 32
    int cur = 0;
    for (int kt = 0; kt < KT; kt++) {
        if (kt + 1 < KT) {
            int k0 = (kt + 1) * 32;
#pragma unroll
            for (int j = 0; j < 2; j++) ra[j] = *(const float4*)(aptr[j] + k0);
#pragma unroll
            for (int j = 0; j < 4; j++) rb[j] = *(const float4*)(bptr[j] + k0);
        }
        const unsigned* ab = As + cur * 128 * LDSS;
        const unsigned* bb = Bs + cur * 256 * LDSS;
#pragma unroll
        for (int kk = 0; kk < 32; kk += 8) {
            unsigned af[2][4];
#pragma unroll
            for (int mi = 0; mi < 2; mi++) {
                int r = mb + mi * 16 + gid;
                af[mi][0] = ab[r * LDSS + kk + tig];
                af[mi][1] = ab[(r + 8) * LDSS + kk + tig];
                af[mi][2] = ab[r * LDSS + kk + tig + 4];
                af[mi][3] = ab[(r + 8) * LDSS + kk + tig + 4];
            }
            unsigned bf1[4][2], bf3[4][2];
#pragma unroll
            for (int ni = 0; ni < 4; ni++) {
                int r = nb + ni * 8 + gid;
                bf1[ni][0] = bb[r * LDSS + kk + tig];
                bf1[ni][1] = bb[r * LDSS + kk + tig + 4];
                bf3[ni][0] = bb[(r + 128) * LDSS + kk + tig];
                bf3[ni][1] = bb[(r + 128) * LDSS + kk + tig + 4];
            }
#pragma unroll
            for (int mi = 0; mi < 2; mi++)
#pragma unroll
                for (int ni = 0; ni < 4; ni++) {
                    mma_tf32(acc1[mi][ni], af[mi], bf1[ni]);
                    mma_tf32(acc3[mi][ni], af[mi], bf3[ni]);
                }
        }
        if (kt + 1 < KT) F1_STORE(cur ^ 1);
        __syncthreads();
        cur ^= 1;
    }
#undef F1_STORE

    // epilogue: u = silu(h1) * h3
#pragma unroll
    for (int mi = 0; mi < 2; mi++) {
#pragma unroll
        for (int half = 0; half < 2; half++) {
            int ml = m0 + mb + mi * 16 + gid + half * 8;
            if (ml < Me) {
                int gi = off + ml;
                float* up = U + (size_t)gi * HDIM;
#pragma unroll
                for (int ni = 0; ni < 4; ni++) {
                    int n = n0 + nb + ni * 8 + tig * 2;
                    float2 v;
                    v.x = silu(acc1[mi][ni][half * 2 + 0]) * acc3[mi][ni][half * 2 + 0];
                    v.y = silu(acc1[mi][ni][half * 2 + 1]) * acc3[mi][ni][half * 2 + 1];
                    *(float2*)(up + n) = v;
                }
            }
        }
    }
}

// ---------------- GEMM2: Y[slot] = w * (U @ W2^T), grouped -------------------
// block tile 128m x 128n, BK=32, 256 threads (8 warps, warp = 64m x 32n)
#define SMEM2_BYTES ((2 * 128 * LDSS + 2 * 128 * LDSS) * 4)
__global__ __launch_bounds__(256, 1) void gemm2(
    const float* __restrict__ Uin,
    const float* __restrict__ W2, const float* __restrict__ sw2,
    float* __restrict__ Yout)
{
    int tileIdx = blockIdx.y;
    if (tileIdx >= g_ntiles) return;
    const int e   = g_tile_e[tileIdx];
    const int m0  = g_tile_m[tileIdx];
    const int off = g_off[e];
    const int Me  = g_off[e + 1] - off;
    const float* B = (e < NEXP) ? (W2 + (size_t)e * DDIM * HDIM) : sw2;
    const int n0 = blockIdx.x * 128;

    extern __shared__ unsigned sm2[];
    unsigned* As = sm2;                      // [2][128*LDSS]
    unsigned* Bs = sm2 + 2 * 128 * LDSS;     // [2][128*LDSS]

    const int tid = threadIdx.x;

    const float* aptr[4]; const float* bptr[4];
#pragma unroll
    for (int j = 0; j < 4; j++) {
        int idx = tid + j * 256;
        int row = idx >> 3, kc = (idx & 7) * 4;
        int ml = m0 + row;
        int gi = off + (ml < Me ? ml : 0);
        aptr[j] = Uin + (size_t)gi * HDIM + kc;
        bptr[j] = B + (size_t)(n0 + row) * HDIM + kc;
    }

    const int wid = tid >> 5, lane = tid & 31;
    const int mb = (wid & 1) * 64, nb = (wid >> 1) * 32;
    const int gid = lane >> 2, tig = lane & 3;

    float acc[4][4][4];
#pragma unroll
    for (int mi = 0; mi < 4; mi++)
#pragma unroll
        for (int ni = 0; ni < 4; ni++)
#pragma unroll
            for (int q = 0; q < 4; q++) acc[mi][ni][q] = 0.f;

    float4 ra[4], rb[4];

#define F2_STORE(buf)                                                                     \
    do {                                                                                  \
        unsigned* ab = As + (buf) * 128 * LDSS;                                           \
        unsigned* bb = Bs + (buf) * 128 * LDSS;                                           \
        _Pragma("unroll")                                                                 \
        for (int j = 0; j < 4; j++) {                                                     \
            int idx = tid + j * 256;                                                      \
            int st = (idx >> 3) * LDSS + (idx & 7) * 4;                                   \
            *(uint4*)(ab + st) = make_uint4(f2tf(ra[j].x), f2tf(ra[j].y),                 \
                                            f2tf(ra[j].z), f2tf(ra[j].w));                \
            *(uint4*)(bb + st) = make_uint4(f2tf(rb[j].x), f2tf(rb[j].y),                 \
                                            f2tf(rb[j].z), f2tf(rb[j].w));                \
        }                                                                                 \
    } while (0)

#pragma unroll
    for (int j = 0; j < 4; j++) { ra[j] = *(const float4*)(aptr[j]); rb[j] = *(const float4*)(bptr[j]); }
    F2_STORE(0);
    __syncthreads();

    const int KT = HDIM / 32;   // 64
    int cur = 0;
    for (int kt = 0; kt < KT; kt++) {
        if (kt + 1 < KT) {
            int k0 = (kt + 1) * 32;
#pragma unroll
            for (int j = 0; j < 4; j++) {
                ra[j] = *(const float4*)(aptr[j] + k0);
                rb[j] = *(const float4*)(bptr[j] + k0);
            }
        }
        const unsigned* ab = As + cur * 128 * LDSS;
        const unsigned* bb = Bs + cur * 128 * LDSS;
#pragma unroll
        for (int kk = 0; kk < 32; kk += 8) {
            unsigned af[4][4];
#pragma unroll
            for (int mi = 0; mi < 4; mi++) {
                int r = mb + mi * 16 + gid;
                af[mi][0] = ab[r * LDSS + kk + tig];
                af[mi][1] = ab[(r + 8) * LDSS + kk + tig];
                af[mi][2] = ab[r * LDSS + kk + tig + 4];
                af[mi][3] = ab[(r + 8) * LDSS + kk + tig + 4];
            }
            unsigned bf[4][2];
#pragma unroll
            for (int ni = 0; ni < 4; ni++) {
                int r = nb + ni * 8 + gid;
                bf[ni][0] = bb[r * LDSS + kk + tig];
                bf[ni][1] = bb[r * LDSS + kk + tig + 4];
            }
#pragma unroll
            for (int mi = 0; mi < 4; mi++)
#pragma unroll
                for (int ni = 0; ni < 4; ni++) mma_tf32(acc[mi][ni], af[mi], bf[ni]);
        }
        if (kt + 1 < KT) F2_STORE(cur ^ 1);
        __syncthreads();
        cur ^= 1;
    }
#undef F2_STORE

    // epilogue: scatter with combine weight
#pragma unroll
    for (int mi = 0; mi < 4; mi++) {
#pragma unroll
        for (int half = 0; half < 2; half++) {
            int ml = m0 + mb + mi * 16 + gid + half * 8;
            if (ml < Me) {
                int gi = off + ml;
                int info = g_rows[gi];
                int slot = (info >> 2) * 3 + (info & 3);
                float w = g_wslot[slot];
                float* yp = Yout + (size_t)slot * DDIM;
#pragma unroll
                for (int ni = 0; ni < 4; ni++) {
                    int n = n0 + nb + ni * 8 + tig * 2;
                    float2 v;
                    v.x = acc[mi][ni][half * 2 + 0] * w;
                    v.y = acc[mi][ni][half * 2 + 1] * w;
                    *(float2*)(yp + n) = v;
                }
            }
        }
    }
}

// ---------------- launch -----------------------------------------------------
extern "C" void kernel_launch(void* const* d_in, const int* in_sizes, int n_in,
                              void* d_out, int out_size)
{
    const float* h   = (const float*)d_in[0];
    const float* sw1 = (const float*)d_in[1];
    const float* sw2 = (const float*)d_in[2];
    const float* sw3 = (const float*)d_in[3];
    const float* W1  = (const float*)d_in[4];
    const float* W2  = (const float*)d_in[5];
    const float* W3  = (const float*)d_in[6];
    const float* Wg  = (const float*)d_in[7];
    float* out = (float*)d_out;

    static bool attr_done = false;
    if (!attr_done) {
        cudaFuncSetAttribute(gemm1_fused, cudaFuncAttributeMaxDynamicSharedMemorySize, SMEM1_BYTES);
        cudaFuncSetAttribute(gemm2,       cudaFuncAttributeMaxDynamicSharedMemorySize, SMEM2_BYTES);
        attr_done = true;
    }

    void *pU, *pY;
    cudaGetSymbolAddress(&pU, g_U);
    cudaGetSymbolAddress(&pY, g_Y);

    zero_kernel<<<1, 32>>>();
    gate_kernel<<<T_TOK / 8, 256>>>(h, Wg);
    setup_kernel<<<1, 1>>>();
    scatter_kernel<<<(T_TOK * TOPK + 255) / 256, 256>>>();

    dim3 grid1(HDIM / 128, MAXTILES);   // 16 x tiles
    gemm1_fused<<<grid1, 512, SMEM1_BYTES>>>(h, W1, sw1, W3, sw3, (float*)pU);

    dim3 grid2(DDIM / 128, MAXTILES);   // 8 x tiles
    gemm2<<<grid2, 256, SMEM2_BYTES>>>((const float*)pU, W2, sw2, (float*)pY);

    combine_kernel<<<(T_TOK * DDIM / 4 + 255) / 256, 256>>>(out);
}

// round 5
// speedup vs baseline: 2.3293x; 1.4915x over previous
#include <cuda_runtime.h>
#include <cstdint>

// Problem constants
#define T_TOK  8192
#define DDIM   1024
#define HDIM   2048
#define NEXP   8
#define TOPK   2
#define ROWS_TOT 24576       // T*K routed rows + T shared rows
#define MAXTILES 200
#define LDH    20            // smem row stride in half2 words (16 data + 4 pad)

// ---------------- scratch ----------------------------------------------------
__device__ unsigned g_U[(size_t)ROWS_TOT * HDIM / 2];   // U = silu(h1)*h3, fp16x2
__device__ float    g_Y[(size_t)ROWS_TOT * DDIM];       // per-slot outputs (scaled)
__device__ int      g_rows [ROWS_TOT];                  // grouped row -> token*4 + k
__device__ float    g_wslot[T_TOK * 3];
__device__ int      g_tok_e[T_TOK * TOPK];
__device__ int      g_cnt [16];
__device__ int      g_fill[16];
__device__ int      g_off [16];
__device__ int      g_tile_e[MAXTILES + 8];
__device__ int      g_tile_m[MAXTILES + 8];
__device__ int      g_ntiles;

// ---------------- small kernels ----------------------------------------------
__global__ void zero_kernel() {
    if (threadIdx.x < 16) { g_cnt[threadIdx.x] = 0; g_fill[threadIdx.x] = 0; }
}

__global__ void gate_kernel(const float* __restrict__ hf, const float* __restrict__ Wg) {
    int wid  = (blockIdx.x * blockDim.x + threadIdx.x) >> 5;
    int lane = threadIdx.x & 31;
    if (wid >= T_TOK) return;
    int t = wid;

    float s[NEXP];
#pragma unroll
    for (int e = 0; e < NEXP; e++) s[e] = 0.f;
    const float* x = hf + (size_t)t * DDIM;
    for (int d = lane; d < DDIM; d += 32) {
        float xv = x[d];
#pragma unroll
        for (int e = 0; e < NEXP; e++) s[e] += xv * Wg[e * DDIM + d];
    }
#pragma unroll
    for (int e = 0; e < NEXP; e++) {
#pragma unroll
        for (int o = 16; o; o >>= 1) s[e] += __shfl_xor_sync(0xffffffffu, s[e], o);
    }
    if (lane == 0) {
        float m = s[0];
#pragma unroll
        for (int e = 1; e < NEXP; e++) m = fmaxf(m, s[e]);
        float p[NEXP];
#pragma unroll
        for (int e = 0; e < NEXP; e++) p[e] = __expf(s[e] - m);
        float v0 = -1.f, v1 = -1.f; int i0 = 0, i1 = 0;
#pragma unroll
        for (int e = 0; e < NEXP; e++) {
            if (p[e] > v0)      { v1 = v0; i1 = i0; v0 = p[e]; i0 = e; }
            else if (p[e] > v1) { v1 = p[e]; i1 = e; }
        }
        float inv = 1.f / (v0 + v1);
        g_tok_e[t * 2 + 0] = i0;
        g_tok_e[t * 2 + 1] = i1;
        g_wslot[t * 3 + 0] = v0 * inv;
        g_wslot[t * 3 + 1] = v1 * inv;
        g_wslot[t * 3 + 2] = 1.f;
        atomicAdd(&g_cnt[i0], 1);
        atomicAdd(&g_cnt[i1], 1);
        g_rows[T_TOK * TOPK + t] = t * 4 + 2;   // shared-expert group rows
    }
}

__global__ void setup_kernel() {
    g_off[0] = 0;
    for (int e = 0; e < NEXP; e++) g_off[e + 1] = g_off[e] + g_cnt[e];
    g_off[NEXP + 1] = g_off[NEXP] + T_TOK;
    int nt = 0;
    for (int e = 0; e <= NEXP; e++) {
        int Me = g_off[e + 1] - g_off[e];
        for (int j = 0; j < Me; j += 128) { g_tile_e[nt] = e; g_tile_m[nt] = j; nt++; }
    }
    g_ntiles = nt;
}

__global__ void scatter_kernel() {
    int i = blockIdx.x * blockDim.x + threadIdx.x;
    if (i >= T_TOK * TOPK) return;
    int e = g_tok_e[i];
    int pos = atomicAdd(&g_fill[e], 1);
    g_rows[g_off[e] + pos] = (i >> 1) * 4 + (i & 1);
}

__global__ void combine_kernel(float* __restrict__ out) {
    int i = blockIdx.x * blockDim.x + threadIdx.x;
    if (i >= T_TOK * DDIM / 4) return;
    int t  = i / (DDIM / 4);
    int d4 = i % (DDIM / 4);
    const float4* Y = (const float4*)g_Y;
    float4 a = Y[(size_t)(t * 3 + 0) * (DDIM / 4) + d4];
    float4 b = Y[(size_t)(t * 3 + 1) * (DDIM / 4) + d4];
    float4 c = Y[(size_t)(t * 3 + 2) * (DDIM / 4) + d4];
    ((float4*)out)[i] = make_float4(a.x + b.x + c.x, a.y + b.y + c.y,
                                    a.z + b.z + c.z, a.w + b.w + c.w);
}

// ---------------- fp16 helpers ----------------------------------------------
__device__ __forceinline__ unsigned f2h2(float lo, float hi) {
    unsigned r;
    asm("cvt.rn.f16x2.f32 %0, %1, %2;" : "=r"(r) : "f"(hi), "f"(lo));
    return r;
}
__device__ __forceinline__ void mma_fp16(float* c, const unsigned* a, const unsigned* b) {
    asm volatile(
        "mma.sync.aligned.m16n8k16.row.col.f32.f16.f16.f32 "
        "{%0,%1,%2,%3}, {%4,%5,%6,%7}, {%8,%9}, {%0,%1,%2,%3};\n"
        : "+f"(c[0]), "+f"(c[1]), "+f"(c[2]), "+f"(c[3])
        : "r"(a[0]), "r"(a[1]), "r"(a[2]), "r"(a[3]), "r"(b[0]), "r"(b[1]));
}
__device__ __forceinline__ float silu(float x) { return x / (1.f + __expf(-x)); }

// ---------------- fused GEMM1: U = silu(A@W1^T) * (A@W3^T), grouped ----------
// block tile 128m x 128h, BK=32, 512 threads (16 warps, warp = 32m x 32h x 2 weights)
#define SMEM1_BYTES ((2 * 128 * LDH + 2 * 256 * LDH) * 4)
__global__ __launch_bounds__(512, 1) void gemm1_fused(
    const float* __restrict__ A,
    const float* __restrict__ W1, const float* __restrict__ sw1,
    const float* __restrict__ W3, const float* __restrict__ sw3,
    unsigned* __restrict__ U)
{
    int tileIdx = blockIdx.y;
    if (tileIdx >= g_ntiles) return;
    const int e   = g_tile_e[tileIdx];
    const int m0  = g_tile_m[tileIdx];
    const int off = g_off[e];
    const int Me  = g_off[e + 1] - off;
    const float* B1 = (e < NEXP) ? (W1 + (size_t)e * HDIM * DDIM) : sw1;
    const float* B3 = (e < NEXP) ? (W3 + (size_t)e * HDIM * DDIM) : sw3;
    const int n0 = blockIdx.x * 128;

    extern __shared__ unsigned sm1[];
    unsigned* As = sm1;                       // [2][128*LDH]
    unsigned* Bs = sm1 + 2 * 128 * LDH;       // [2][256*LDH]

    const int tid = threadIdx.x;

    // ---- loader setup: A = 2 x float4 / thread, B = 4 x float4 / thread ----
    const float* aptr[2];
#pragma unroll
    for (int j = 0; j < 2; j++) {
        int idx = tid + j * 512;
        int row = idx >> 3, kc = (idx & 7) * 4;
        int ml = m0 + row;
        int gi = off + (ml < Me ? ml : 0);
        int tok = g_rows[gi] >> 2;
        aptr[j] = A + (size_t)tok * DDIM + kc;
    }
    const float* bptr[4];
#pragma unroll
    for (int j = 0; j < 4; j++) {
        int idx = tid + j * 512;
        int row = idx >> 3, kc = (idx & 7) * 4;
        const float* Bsrc = (row < 128) ? (B1 + (size_t)(n0 + row) * DDIM)
                                        : (B3 + (size_t)(n0 + row - 128) * DDIM);
        bptr[j] = Bsrc + kc;
    }

    const int wid = tid >> 5, lane = tid & 31;
    const int mb = (wid & 3) * 32, nb = (wid >> 2) * 32;
    const int gid = lane >> 2, tig = lane & 3;

    float acc1[2][4][4], acc3[2][4][4];
#pragma unroll
    for (int mi = 0; mi < 2; mi++)
#pragma unroll
        for (int ni = 0; ni < 4; ni++)
#pragma unroll
            for (int q = 0; q < 4; q++) { acc1[mi][ni][q] = 0.f; acc3[mi][ni][q] = 0.f; }

    float4 ra[2], rb[4];

#define F1_STORE(buf)                                                                     \
    do {                                                                                  \
        unsigned* ab = As + (buf) * 128 * LDH;                                            \
        unsigned* bb = Bs + (buf) * 256 * LDH;                                            \
        _Pragma("unroll")                                                                 \
        for (int j = 0; j < 2; j++) {                                                     \
            int idx = tid + j * 512;                                                      \
            int st = (idx >> 3) * LDH + (idx & 7) * 2;                                    \
            *(uint2*)(ab + st) = make_uint2(f2h2(ra[j].x, ra[j].y), f2h2(ra[j].z, ra[j].w)); \
        }                                                                                 \
        _Pragma("unroll")                                                                 \
        for (int j = 0; j < 4; j++) {                                                     \
            int idx = tid + j * 512;                                                      \
            int st = (idx >> 3) * LDH + (idx & 7) * 2;                                    \
            *(uint2*)(bb + st) = make_uint2(f2h2(rb[j].x, rb[j].y), f2h2(rb[j].z, rb[j].w)); \
        }                                                                                 \
    } while (0)

    // prologue
#pragma unroll
    for (int j = 0; j < 2; j++) ra[j] = *(const float4*)(aptr[j]);
#pragma unroll
    for (int j = 0; j < 4; j++) rb[j] = *(const float4*)(bptr[j]);
    F1_STORE(0);
    __syncthreads();

    const int KT = DDIM / 32;   // 32
    int cur = 0;
    for (int kt = 0; kt < KT; kt++) {
        if (kt + 1 < KT) {
            int k0 = (kt + 1) * 32;
#pragma unroll
            for (int j = 0; j < 2; j++) ra[j] = *(const float4*)(aptr[j] + k0);
#pragma unroll
            for (int j = 0; j < 4; j++) rb[j] = *(const float4*)(bptr[j] + k0);
        }
        const unsigned* ab = As + cur * 128 * LDH;
        const unsigned* bb = Bs + cur * 256 * LDH;
#pragma unroll
        for (int kc = 0; kc < 2; kc++) {          // two k16 chunks
            const int kw = kc * 8;                // word offset of chunk
            unsigned af[2][4];
#pragma unroll
            for (int mi = 0; mi < 2; mi++) {
                int r = mb + mi * 16 + gid;
                af[mi][0] = ab[r * LDH + kw + tig];
                af[mi][1] = ab[(r + 8) * LDH + kw + tig];
                af[mi][2] = ab[r * LDH + kw + tig + 4];
                af[mi][3] = ab[(r + 8) * LDH + kw + tig + 4];
            }
            unsigned bf1[4][2], bf3[4][2];
#pragma unroll
            for (int ni = 0; ni < 4; ni++) {
                int r = nb + ni * 8 + gid;
                bf1[ni][0] = bb[r * LDH + kw + tig];
                bf1[ni][1] = bb[r * LDH + kw + tig + 4];
                bf3[ni][0] = bb[(r + 128) * LDH + kw + tig];
                bf3[ni][1] = bb[(r + 128) * LDH + kw + tig + 4];
            }
#pragma unroll
            for (int mi = 0; mi < 2; mi++)
#pragma unroll
                for (int ni = 0; ni < 4; ni++) {
                    mma_fp16(acc1[mi][ni], af[mi], bf1[ni]);
                    mma_fp16(acc3[mi][ni], af[mi], bf3[ni]);
                }
        }
        if (kt + 1 < KT) F1_STORE(cur ^ 1);
        __syncthreads();
        cur ^= 1;
    }
#undef F1_STORE

    // epilogue: u = silu(h1) * h3  (stored as half2)
#pragma unroll
    for (int mi = 0; mi < 2; mi++) {
#pragma unroll
        for (int half = 0; half < 2; half++) {
            int ml = m0 + mb + mi * 16 + gid + half * 8;
            if (ml < Me) {
                int gi = off + ml;
                unsigned* up = U + ((size_t)gi * HDIM) / 2;
#pragma unroll
                for (int ni = 0; ni < 4; ni++) {
                    int n = n0 + nb + ni * 8 + tig * 2;
                    float vx = silu(acc1[mi][ni][half * 2 + 0]) * acc3[mi][ni][half * 2 + 0];
                    float vy = silu(acc1[mi][ni][half * 2 + 1]) * acc3[mi][ni][half * 2 + 1];
                    up[n >> 1] = f2h2(vx, vy);
                }
            }
        }
    }
}

// ---------------- GEMM2: Y[slot] = w * (U @ W2^T), grouped -------------------
// block tile 128m x 128n, BK=32, 256 threads (8 warps, warp = 64m x 32n)
#define SMEM2_BYTES ((2 * 128 * LDH + 2 * 128 * LDH) * 4)
__global__ __launch_bounds__(256, 1) void gemm2(
    const unsigned* __restrict__ Uin,
    const float* __restrict__ W2, const float* __restrict__ sw2,
    float* __restrict__ Yout)
{
    int tileIdx = blockIdx.y;
    if (tileIdx >= g_ntiles) return;
    const int e   = g_tile_e[tileIdx];
    const int m0  = g_tile_m[tileIdx];
    const int off = g_off[e];
    const int Me  = g_off[e + 1] - off;
    const float* B = (e < NEXP) ? (W2 + (size_t)e * DDIM * HDIM) : sw2;
    const int n0 = blockIdx.x * 128;

    extern __shared__ unsigned sm2[];
    unsigned* As = sm2;                      // [2][128*LDH]
    unsigned* Bs = sm2 + 2 * 128 * LDH;      // [2][128*LDH]

    const int tid = threadIdx.x;

    const uint2* aptr[4]; const float* bptr[4];
#pragma unroll
    for (int j = 0; j < 4; j++) {
        int idx = tid + j * 256;
        int row = idx >> 3, kc = (idx & 7) * 4;
        int ml = m0 + row;
        int gi = off + (ml < Me ? ml : 0);
        aptr[j] = (const uint2*)(Uin + (size_t)gi * (HDIM / 2) + (kc >> 1));
        bptr[j] = B + (size_t)(n0 + row) * HDIM + kc;
    }

    const int wid = tid >> 5, lane = tid & 31;
    const int mb = (wid & 1) * 64, nb = (wid >> 1) * 32;
    const int gid = lane >> 2, tig = lane & 3;

    float acc[4][4][4];
#pragma unroll
    for (int mi = 0; mi < 4; mi++)
#pragma unroll
        for (int ni = 0; ni < 4; ni++)
#pragma unroll
            for (int q = 0; q < 4; q++) acc[mi][ni][q] = 0.f;

    uint2 ra[4]; float4 rb[4];

#define F2_STORE(buf)                                                                     \
    do {                                                                                  \
        unsigned* ab = As + (buf) * 128 * LDH;                                            \
        unsigned* bb = Bs + (buf) * 128 * LDH;                                            \
        _Pragma("unroll")                                                                 \
        for (int j = 0; j < 4; j++) {                                                     \
            int idx = tid + j * 256;                                                      \
            int st = (idx >> 3) * LDH + (idx & 7) * 2;                                    \
            *(uint2*)(ab + st) = ra[j];                                                   \
            *(uint2*)(bb + st) = make_uint2(f2h2(rb[j].x, rb[j].y), f2h2(rb[j].z, rb[j].w)); \
        }                                                                                 \
    } while (0)

#pragma unroll
    for (int j = 0; j < 4; j++) { ra[j] = *(aptr[j]); rb[j] = *(const float4*)(bptr[j]); }
    F2_STORE(0);
    __syncthreads();

    const int KT = HDIM / 32;   // 64
    int cur = 0;
    for (int kt = 0; kt < KT; kt++) {
        if (kt + 1 < KT) {
            int k0f = (kt + 1) * 32;            // in halves (k elements)
#pragma unroll
            for (int j = 0; j < 4; j++) {
                ra[j] = *(aptr[j] + (k0f >> 2));   // uint2 = 4 halves
                rb[j] = *(const float4*)(bptr[j] + k0f);
            }
        }
        const unsigned* ab = As + cur * 128 * LDH;
        const unsigned* bb = Bs + cur * 128 * LDH;
#pragma unroll
        for (int kc = 0; kc < 2; kc++) {
            const int kw = kc * 8;
            unsigned af[4][4];
#pragma unroll
            for (int mi = 0; mi < 4; mi++) {
                int r = mb + mi * 16 + gid;
                af[mi][0] = ab[r * LDH + kw + tig];
                af[mi][1] = ab[(r + 8) * LDH + kw + tig];
                af[mi][2] = ab[r * LDH + kw + tig + 4];
                af[mi][3] = ab[(r + 8) * LDH + kw + tig + 4];
            }
            unsigned bf[4][2];
#pragma unroll
            for (int ni = 0; ni < 4; ni++) {
                int r = nb + ni * 8 + gid;
                bf[ni][0] = bb[r * LDH + kw + tig];
                bf[ni][1] = bb[r * LDH + kw + tig + 4];
            }
#pragma unroll
            for (int mi = 0; mi < 4; mi++)
#pragma unroll
                for (int ni = 0; ni < 4; ni++) mma_fp16(acc[mi][ni], af[mi], bf[ni]);
        }
        if (kt + 1 < KT) F2_STORE(cur ^ 1);
        __syncthreads();
        cur ^= 1;
    }
#undef F2_STORE

    // epilogue: scatter with combine weight
#pragma unroll
    for (int mi = 0; mi < 4; mi++) {
#pragma unroll
        for (int half = 0; half < 2; half++) {
            int ml = m0 + mb + mi * 16 + gid + half * 8;
            if (ml < Me) {
                int gi = off + ml;
                int info = g_rows[gi];
                int slot = (info >> 2) * 3 + (info & 3);
                float w = g_wslot[slot];
                float* yp = Yout + (size_t)slot * DDIM;
#pragma unroll
                for (int ni = 0; ni < 4; ni++) {
                    int n = n0 + nb + ni * 8 + tig * 2;
                    float2 v;
                    v.x = acc[mi][ni][half * 2 + 0] * w;
                    v.y = acc[mi][ni][half * 2 + 1] * w;
                    *(float2*)(yp + n) = v;
                }
            }
        }
    }
}

// ---------------- launch -----------------------------------------------------
extern "C" void kernel_launch(void* const* d_in, const int* in_sizes, int n_in,
                              void* d_out, int out_size)
{
    const float* h   = (const float*)d_in[0];
    const float* sw1 = (const float*)d_in[1];
    const float* sw2 = (const float*)d_in[2];
    const float* sw3 = (const float*)d_in[3];
    const float* W1  = (const float*)d_in[4];
    const float* W2  = (const float*)d_in[5];
    const float* W3  = (const float*)d_in[6];
    const float* Wg  = (const float*)d_in[7];
    float* out = (float*)d_out;

    static bool attr_done = false;
    if (!attr_done) {
        cudaFuncSetAttribute(gemm1_fused, cudaFuncAttributeMaxDynamicSharedMemorySize, SMEM1_BYTES);
        cudaFuncSetAttribute(gemm2,       cudaFuncAttributeMaxDynamicSharedMemorySize, SMEM2_BYTES);
        attr_done = true;
    }

    void *pU, *pY;
    cudaGetSymbolAddress(&pU, g_U);
    cudaGetSymbolAddress(&pY, g_Y);

    zero_kernel<<<1, 32>>>();
    gate_kernel<<<T_TOK / 8, 256>>>(h, Wg);
    setup_kernel<<<1, 1>>>();
    scatter_kernel<<<(T_TOK * TOPK + 255) / 256, 256>>>();

    dim3 grid1(HDIM / 128, MAXTILES);   // 16 x tiles
    gemm1_fused<<<grid1, 512, SMEM1_BYTES>>>(h, W1, sw1, W3, sw3, (unsigned*)pU);

    dim3 grid2(DDIM / 128, MAXTILES);   // 8 x tiles
    gemm2<<<grid2, 256, SMEM2_BYTES>>>((const unsigned*)pU, W2, sw2, (float*)pY);

    combine_kernel<<<(T_TOK * DDIM / 4 + 255) / 256, 256>>>(out);
}

// round 6
// speedup vs baseline: 3.0233x; 1.2979x over previous
#include <cuda_runtime.h>
#include <cstdint>

// Problem constants
#define T_TOK  8192
#define DDIM   1024
#define HDIM   2048
#define NEXP   8
#define TOPK   2
#define ROWS_TOT 24576       // T*K routed rows + T shared rows
#define MAXTILES 200

// ---------------- scratch (fp16 stored as raw bits) --------------------------
__device__ unsigned short g_Ah[(size_t)T_TOK * DDIM];                  // h in fp16
__device__ unsigned g_W1h[(size_t)(NEXP + 1) * HDIM * DDIM / 2];       // expert 8 = shared
__device__ unsigned g_W3h[(size_t)(NEXP + 1) * HDIM * DDIM / 2];
__device__ unsigned g_W2h[(size_t)(NEXP + 1) * DDIM * HDIM / 2];
__device__ unsigned g_U[(size_t)ROWS_TOT * HDIM / 2];                  // U = silu(h1)*h3, fp16x2
__device__ float    g_Y[(size_t)ROWS_TOT * DDIM];
__device__ int      g_rows [ROWS_TOT];
__device__ float    g_wslot[T_TOK * 3];
__device__ int      g_tok_e[T_TOK * TOPK];
__device__ int      g_cnt [16];
__device__ int      g_fill[16];
__device__ int      g_off [16];
__device__ int      g_tile_e[MAXTILES + 8];
__device__ int      g_tile_m[MAXTILES + 8];
__device__ int      g_ntiles;

// ---------------- helpers ----------------------------------------------------
__device__ __forceinline__ uint32_t smem_u32(const void* p) {
    uint32_t a;
    asm("{ .reg .u64 t; cvta.to.shared.u64 t, %1; cvt.u32.u64 %0, t; }" : "=r"(a) : "l"(p));
    return a;
}
__device__ __forceinline__ unsigned f2h2(float lo, float hi) {
    unsigned r;
    asm("cvt.rn.f16x2.f32 %0, %1, %2;" : "=r"(r) : "f"(hi), "f"(lo));
    return r;
}
__device__ __forceinline__ void mma_fp16(float* c, const unsigned* a, const unsigned* b) {
    asm volatile(
        "mma.sync.aligned.m16n8k16.row.col.f32.f16.f16.f32 "
        "{%0,%1,%2,%3}, {%4,%5,%6,%7}, {%8,%9}, {%0,%1,%2,%3};\n"
        : "+f"(c[0]), "+f"(c[1]), "+f"(c[2]), "+f"(c[3])
        : "r"(a[0]), "r"(a[1]), "r"(a[2]), "r"(a[3]), "r"(b[0]), "r"(b[1]));
}
__device__ __forceinline__ void ldsm4(unsigned* r, uint32_t addr) {
    asm volatile("ldmatrix.sync.aligned.m8n8.x4.shared.b16 {%0,%1,%2,%3}, [%4];"
        : "=r"(r[0]), "=r"(r[1]), "=r"(r[2]), "=r"(r[3]) : "r"(addr));
}
__device__ __forceinline__ float silu(float x) { return x / (1.f + __expf(-x)); }

#define CPA16(sm, gm) asm volatile("cp.async.cg.shared.global [%0], [%1], 16;" :: "r"(sm), "l"(gm))
#define CPCOMMIT()    asm volatile("cp.async.commit_group;" ::: "memory")
#define CPWAIT2()     asm volatile("cp.async.wait_group 2;" ::: "memory")

// ---------------- small kernels ----------------------------------------------
__global__ void zero_kernel() {
    if (threadIdx.x < 16) { g_cnt[threadIdx.x] = 0; g_fill[threadIdx.x] = 0; }
}

__global__ void cvt_kernel(const float4* __restrict__ src, uint2* __restrict__ dst, int n4) {
    int i = blockIdx.x * blockDim.x + threadIdx.x;
    if (i >= n4) return;
    float4 v = src[i];
    dst[i] = make_uint2(f2h2(v.x, v.y), f2h2(v.z, v.w));
}

// gate + convert h to fp16
__global__ void gate_kernel(const float* __restrict__ hf, const float* __restrict__ Wg) {
    int wid  = (blockIdx.x * blockDim.x + threadIdx.x) >> 5;
    int lane = threadIdx.x & 31;
    if (wid >= T_TOK) return;
    int t = wid;

    float s[NEXP];
#pragma unroll
    for (int e = 0; e < NEXP; e++) s[e] = 0.f;
    const float* x = hf + (size_t)t * DDIM;
    for (int d = lane; d < DDIM; d += 32) {
        float xv = x[d];
        unsigned short hb;
        asm("cvt.rn.f16.f32 %0, %1;" : "=h"(hb) : "f"(xv));
        g_Ah[(size_t)t * DDIM + d] = hb;
#pragma unroll
        for (int e = 0; e < NEXP; e++) s[e] += xv * Wg[e * DDIM + d];
    }
#pragma unroll
    for (int e = 0; e < NEXP; e++) {
#pragma unroll
        for (int o = 16; o; o >>= 1) s[e] += __shfl_xor_sync(0xffffffffu, s[e], o);
    }
    if (lane == 0) {
        float m = s[0];
#pragma unroll
        for (int e = 1; e < NEXP; e++) m = fmaxf(m, s[e]);
        float p[NEXP];
#pragma unroll
        for (int e = 0; e < NEXP; e++) p[e] = __expf(s[e] - m);
        float v0 = -1.f, v1 = -1.f; int i0 = 0, i1 = 0;
#pragma unroll
        for (int e = 0; e < NEXP; e++) {
            if (p[e] > v0)      { v1 = v0; i1 = i0; v0 = p[e]; i0 = e; }
            else if (p[e] > v1) { v1 = p[e]; i1 = e; }
        }
        float inv = 1.f / (v0 + v1);
        g_tok_e[t * 2 + 0] = i0;
        g_tok_e[t * 2 + 1] = i1;
        g_wslot[t * 3 + 0] = v0 * inv;
        g_wslot[t * 3 + 1] = v1 * inv;
        g_wslot[t * 3 + 2] = 1.f;
        atomicAdd(&g_cnt[i0], 1);
        atomicAdd(&g_cnt[i1], 1);
        g_rows[T_TOK * TOPK + t] = t * 4 + 2;
    }
}

__global__ void setup_kernel() {
    g_off[0] = 0;
    for (int e = 0; e < NEXP; e++) g_off[e + 1] = g_off[e] + g_cnt[e];
    g_off[NEXP + 1] = g_off[NEXP] + T_TOK;
    int nt = 0;
    for (int e = 0; e <= NEXP; e++) {
        int Me = g_off[e + 1] - g_off[e];
        for (int j = 0; j < Me; j += 128) { g_tile_e[nt] = e; g_tile_m[nt] = j; nt++; }
    }
    g_ntiles = nt;
}

__global__ void scatter_kernel() {
    int i = blockIdx.x * blockDim.x + threadIdx.x;
    if (i >= T_TOK * TOPK) return;
    int e = g_tok_e[i];
    int pos = atomicAdd(&g_fill[e], 1);
    g_rows[g_off[e] + pos] = (i >> 1) * 4 + (i & 1);
}

__global__ void combine_kernel(float* __restrict__ out) {
    int i = blockIdx.x * blockDim.x + threadIdx.x;
    if (i >= T_TOK * DDIM / 4) return;
    int t  = i / (DDIM / 4);
    int d4 = i % (DDIM / 4);
    const float4* Y = (const float4*)g_Y;
    float4 a = Y[(size_t)(t * 3 + 0) * (DDIM / 4) + d4];
    float4 b = Y[(size_t)(t * 3 + 1) * (DDIM / 4) + d4];
    float4 c = Y[(size_t)(t * 3 + 2) * (DDIM / 4) + d4];
    ((float4*)out)[i] = make_float4(a.x + b.x + c.x, a.y + b.y + c.y,
                                    a.z + b.z + c.z, a.w + b.w + c.w);
}

// ---------------- fused GEMM1: U = silu(A@W1^T) * (A@W3^T) -------------------
// 128m x 128h tile, BK=32, 512 threads (16 warps of 32m x 32h x 2 weights),
// 4-stage cp.async pipeline, ldmatrix fragments, 80B padded rows.
#define NST    4
#define A1STG  (128 * 80)
#define B1STG  (256 * 80)
#define STG1   (A1STG + B1STG)
#define SMEM1_BYTES (NST * STG1)     // 122880

__global__ __launch_bounds__(512, 1) void gemm1_fused() {
    const int tileIdx = blockIdx.y;
    if (tileIdx >= g_ntiles) return;
    const int e   = g_tile_e[tileIdx];
    const int m0  = g_tile_m[tileIdx];
    const int off = g_off[e];
    const int Me  = g_off[e + 1] - off;
    const int n0  = blockIdx.x * 128;
    const size_t wst = (size_t)HDIM * DDIM / 2;   // half2 words per expert

    extern __shared__ unsigned char smem[];
    const uint32_t smb = smem_u32(smem);
    const int tid  = threadIdx.x;
    const int wid  = tid >> 5, lane = tid & 31;

    // ---- loader: 3 x 16B chunks / thread / stage ----
    const char* gsrc[3];
    uint32_t    sdst[3];
#pragma unroll
    for (int j = 0; j < 3; j++) {
        int id = tid + j * 512;
        if (id < 512) {
            int row = id >> 2, kc = id & 3;
            int ml = m0 + row;
            int gi = off + (ml < Me ? ml : 0);
            int tok = g_rows[gi] >> 2;
            gsrc[j] = (const char*)g_Ah + ((size_t)tok * DDIM + kc * 8) * 2;
            sdst[j] = (uint32_t)(row * 80 + kc * 16);
        } else {
            int bid = id - 512;
            int row = bid >> 2, kc = bid & 3;      // 0..255
            const unsigned* W = (row < 128)
                ? (g_W1h + (size_t)e * wst + (size_t)(n0 + row) * (DDIM / 2))
                : (g_W3h + (size_t)e * wst + (size_t)(n0 + row - 128) * (DDIM / 2));
            gsrc[j] = (const char*)W + kc * 16;
            sdst[j] = (uint32_t)(A1STG + row * 80 + kc * 16);
        }
    }

#define G1_ISSUE(s) do {                                                    \
        uint32_t _b = smb + ((s) & 3) * STG1;                               \
        size_t _go = (size_t)(s) * 64;                                      \
        _Pragma("unroll")                                                   \
        for (int j = 0; j < 3; j++) CPA16(_b + sdst[j], gsrc[j] + _go);     \
    } while (0)

    const int mb = (wid & 3) * 32, nb = (wid >> 2) * 32;
    const uint32_t afl = (lane & 15) * 80 + (lane >> 4) * 16;
    const int gid = lane >> 2, tig = lane & 3;

    float acc1[2][4][4], acc3[2][4][4];
#pragma unroll
    for (int mi = 0; mi < 2; mi++)
#pragma unroll
        for (int ni = 0; ni < 4; ni++)
#pragma unroll
            for (int q = 0; q < 4; q++) { acc1[mi][ni][q] = 0.f; acc3[mi][ni][q] = 0.f; }

    // prologue: stages 0..2
#pragma unroll
    for (int s = 0; s < NST - 1; s++) { G1_ISSUE(s); CPCOMMIT(); }

    const int KT = DDIM / 32;    // 32
    for (int kt = 0; kt < KT; kt++) {
        CPWAIT2();
        __syncthreads();
        int pf = kt + NST - 1;
        if (pf < KT) G1_ISSUE(pf);
        CPCOMMIT();

        const uint32_t Ab = smb + (kt & 3) * STG1;
        const uint32_t Bb = Ab + A1STG;
#pragma unroll
        for (int kc = 0; kc < 2; kc++) {
            unsigned af[2][4];
#pragma unroll
            for (int mi = 0; mi < 2; mi++)
                ldsm4(af[mi], Ab + (mb + mi * 16) * 80 + afl + kc * 32);
            unsigned b1f[2][4], b3f[2][4];
#pragma unroll
            for (int p = 0; p < 2; p++) {
                ldsm4(b1f[p], Bb + (nb + p * 16) * 80 + afl + kc * 32);
                ldsm4(b3f[p], Bb + (128 + nb + p * 16) * 80 + afl + kc * 32);
            }
#pragma unroll
            for (int mi = 0; mi < 2; mi++)
#pragma unroll
                for (int ni = 0; ni < 4; ni++) {
                    const int p = ni >> 1, s = ni & 1;
                    unsigned bb1[2] = { b1f[p][s], b1f[p][s + 2] };
                    unsigned bb3[2] = { b3f[p][s], b3f[p][s + 2] };
                    mma_fp16(acc1[mi][ni], af[mi], bb1);
                    mma_fp16(acc3[mi][ni], af[mi], bb3);
                }
        }
    }
#undef G1_ISSUE

    // epilogue: u = silu(h1)*h3 as fp16x2
#pragma unroll
    for (int mi = 0; mi < 2; mi++) {
#pragma unroll
        for (int half = 0; half < 2; half++) {
            int ml = m0 + mb + mi * 16 + gid + half * 8;
            if (ml < Me) {
                int gi = off + ml;
                unsigned* up = g_U + (size_t)gi * (HDIM / 2);
#pragma unroll
                for (int ni = 0; ni < 4; ni++) {
                    int n = n0 + nb + ni * 8 + tig * 2;
                    float vx = silu(acc1[mi][ni][half * 2 + 0]) * acc3[mi][ni][half * 2 + 0];
                    float vy = silu(acc1[mi][ni][half * 2 + 1]) * acc3[mi][ni][half * 2 + 1];
                    up[n >> 1] = f2h2(vx, vy);
                }
            }
        }
    }
}

// ---------------- GEMM2: Y[slot] = w * (U @ W2^T) ----------------------------
// 128m x 128n tile, BK=32, 256 threads (8 warps of 64m x 32n), 4-stage cp.async.
#define A2STG  (128 * 80)
#define B2STG  (128 * 80)
#define STG2   (A2STG + B2STG)
#define SMEM2_BYTES (NST * STG2)     // 81920

__global__ __launch_bounds__(256, 1) void gemm2() {
    const int tileIdx = blockIdx.y;
    if (tileIdx >= g_ntiles) return;
    const int e   = g_tile_e[tileIdx];
    const int m0  = g_tile_m[tileIdx];
    const int off = g_off[e];
    const int Me  = g_off[e + 1] - off;
    const int n0  = blockIdx.x * 128;
    const size_t wst = (size_t)DDIM * HDIM / 2;

    extern __shared__ unsigned char smem[];
    const uint32_t smb = smem_u32(smem);
    const int tid = threadIdx.x;
    const int wid = tid >> 5, lane = tid & 31;

    const char* gsrc[4];
    uint32_t    sdst[4];
#pragma unroll
    for (int j = 0; j < 4; j++) {
        int id = tid + j * 256;
        if (id < 512) {
            int row = id >> 2, kc = id & 3;
            int ml = m0 + row;
            int gi = off + (ml < Me ? ml : 0);
            gsrc[j] = (const char*)g_U + ((size_t)gi * HDIM + kc * 8) * 2;
            sdst[j] = (uint32_t)(row * 80 + kc * 16);
        } else {
            int bid = id - 512;
            int row = bid >> 2, kc = bid & 3;
            gsrc[j] = (const char*)(g_W2h + (size_t)e * wst
                                    + (size_t)(n0 + row) * (HDIM / 2)) + kc * 16;
            sdst[j] = (uint32_t)(A2STG + row * 80 + kc * 16);
        }
    }

#define G2_ISSUE(s) do {                                                    \
        uint32_t _b = smb + ((s) & 3) * STG2;                               \
        size_t _go = (size_t)(s) * 64;                                      \
        _Pragma("unroll")                                                   \
        for (int j = 0; j < 4; j++) CPA16(_b + sdst[j], gsrc[j] + _go);     \
    } while (0)

    const int mb = (wid & 1) * 64, nb = (wid >> 1) * 32;
    const uint32_t afl = (lane & 15) * 80 + (lane >> 4) * 16;
    const int gid = lane >> 2, tig = lane & 3;

    float acc[4][4][4];
#pragma unroll
    for (int mi = 0; mi < 4; mi++)
#pragma unroll
        for (int ni = 0; ni < 4; ni++)
#pragma unroll
            for (int q = 0; q < 4; q++) acc[mi][ni][q] = 0.f;

#pragma unroll
    for (int s = 0; s < NST - 1; s++) { G2_ISSUE(s); CPCOMMIT(); }

    const int KT = HDIM / 32;    // 64
    for (int kt = 0; kt < KT; kt++) {
        CPWAIT2();
        __syncthreads();
        int pf = kt + NST - 1;
        if (pf < KT) G2_ISSUE(pf);
        CPCOMMIT();

        const uint32_t Ab = smb + (kt & 3) * STG2;
        const uint32_t Bb = Ab + A2STG;
#pragma unroll
        for (int kc = 0; kc < 2; kc++) {
            unsigned af[4][4];
#pragma unroll
            for (int mi = 0; mi < 4; mi++)
                ldsm4(af[mi], Ab + (mb + mi * 16) * 80 + afl + kc * 32);
            unsigned bf[2][4];
#pragma unroll
            for (int p = 0; p < 2; p++)
                ldsm4(bf[p], Bb + (nb + p * 16) * 80 + afl + kc * 32);
#pragma unroll
            for (int mi = 0; mi < 4; mi++)
#pragma unroll
                for (int ni = 0; ni < 4; ni++) {
                    const int p = ni >> 1, s = ni & 1;
                    unsigned bb[2] = { bf[p][s], bf[p][s + 2] };
                    mma_fp16(acc[mi][ni], af[mi], bb);
                }
        }
    }
#undef G2_ISSUE

    // epilogue: scale + scatter
#pragma unroll
    for (int mi = 0; mi < 4; mi++) {
#pragma unroll
        for (int half = 0; half < 2; half++) {
            int ml = m0 + mb + mi * 16 + gid + half * 8;
            if (ml < Me) {
                int gi = off + ml;
                int info = g_rows[gi];
                int slot = (info >> 2) * 3 + (info & 3);
                float w = g_wslot[slot];
                float* yp = g_Y + (size_t)slot * DDIM;
#pragma unroll
                for (int ni = 0; ni < 4; ni++) {
                    int n = n0 + nb + ni * 8 + tig * 2;
                    float2 v;
                    v.x = acc[mi][ni][half * 2 + 0] * w;
                    v.y = acc[mi][ni][half * 2 + 1] * w;
                    *(float2*)(yp + n) = v;
                }
            }
        }
    }
}

// ---------------- launch -----------------------------------------------------
extern "C" void kernel_launch(void* const* d_in, const int* in_sizes, int n_in,
                              void* d_out, int out_size)
{
    const float* h   = (const float*)d_in[0];
    const float* sw1 = (const float*)d_in[1];
    const float* sw2 = (const float*)d_in[2];
    const float* sw3 = (const float*)d_in[3];
    const float* W1  = (const float*)d_in[4];
    const float* W2  = (const float*)d_in[5];
    const float* W3  = (const float*)d_in[6];
    const float* Wg  = (const float*)d_in[7];
    float* out = (float*)d_out;

    static bool attr_done = false;
    if (!attr_done) {
        cudaFuncSetAttribute(gemm1_fused, cudaFuncAttributeMaxDynamicSharedMemorySize, SMEM1_BYTES);
        cudaFuncSetAttribute(gemm2,       cudaFuncAttributeMaxDynamicSharedMemorySize, SMEM2_BYTES);
        attr_done = true;
    }

    void *pW1h, *pW3h, *pW2h;
    cudaGetSymbolAddress(&pW1h, g_W1h);
    cudaGetSymbolAddress(&pW3h, g_W3h);
    cudaGetSymbolAddress(&pW2h, g_W2h);

    const size_t wwords = (size_t)HDIM * DDIM / 2;   // half2 words per expert
    const int nbig = NEXP * HDIM * DDIM / 4;         // float4 count, expert block
    const int nsh  = HDIM * DDIM / 4;

    zero_kernel<<<1, 32>>>();
    gate_kernel<<<T_TOK / 8, 256>>>(h, Wg);

    cvt_kernel<<<(nbig + 255) / 256, 256>>>((const float4*)W1, (uint2*)pW1h, nbig);
    cvt_kernel<<<(nsh  + 255) / 256, 256>>>((const float4*)sw1,
        (uint2*)((unsigned*)pW1h + NEXP * wwords), nsh);
    cvt_kernel<<<(nbig + 255) / 256, 256>>>((const float4*)W3, (uint2*)pW3h, nbig);
    cvt_kernel<<<(nsh  + 255) / 256, 256>>>((const float4*)sw3,
        (uint2*)((unsigned*)pW3h + NEXP * wwords), nsh);
    cvt_kernel<<<(nbig + 255) / 256, 256>>>((const float4*)W2, (uint2*)pW2h, nbig);
    cvt_kernel<<<(nsh  + 255) / 256, 256>>>((const float4*)sw2,
        (uint2*)((unsigned*)pW2h + NEXP * wwords), nsh);

    setup_kernel<<<1, 1>>>();
    scatter_kernel<<<(T_TOK * TOPK + 255) / 256, 256>>>();

    dim3 grid1(HDIM / 128, MAXTILES);
    gemm1_fused<<<grid1, 512, SMEM1_BYTES>>>();

    dim3 grid2(DDIM / 128, MAXTILES);
    gemm2<<<grid2, 256, SMEM2_BYTES>>>();

    combine_kernel<<<(T_TOK * DDIM / 4 + 255) / 256, 256>>>(out);
}